// round 6
// baseline (speedup 1.0000x reference)
#include <cuda_runtime.h>
#include <cuda_bf16.h>
#include <cstdint>

// DynamicMaskHead: 128 instances, MLP 10 -> 8 -> 8 -> 1 over 160x160 px (fp32).
// cp.async (LDGSTS) double-buffered smem pipeline: in-flight feature data lives
// in shared memory, not registers, so DRAM latency hiding is decoupled from
// occupancy/register pressure. Compute = R2's packed fma.rn.f32x2 inner loops.

#define NINST 128
#define CIN   10
#define CMID  8
#define HW    25600
#define HW4   (HW / 4)          // 6400 float4 per channel-plane per instance
#define TPB   128
#define TILE4 256               // float4 per tile (1024 pixels)
#define NSTAGE 2
#define TILES_PER_CTA 5         // grid.x = 5 -> 25 tiles per instance
#define CTAS_X 5

#define SMEM_TILE_F4 (CIN * TILE4)              // 2560 float4 per stage
#define DYN_SMEM_BYTES (NSTAGE * SMEM_TILE_F4 * 16)   // 81920

__device__ __forceinline__ float2 ffma2(float2 a, float2 b, float2 c) {
    float2 d;
    asm("fma.rn.f32x2 %0, %1, %2, %3;"
        : "=l"(reinterpret_cast<unsigned long long&>(d))
        : "l"(reinterpret_cast<unsigned long long&>(a)),
          "l"(reinterpret_cast<unsigned long long&>(b)),
          "l"(reinterpret_cast<unsigned long long&>(c)));
    return d;
}

__device__ __forceinline__ float2 relu2(float2 a) {
    return make_float2(fmaxf(a.x, 0.0f), fmaxf(a.y, 0.0f));
}

__device__ __forceinline__ void cp16(uint32_t dst_smem, const float4* src) {
    asm volatile("cp.async.cg.shared.global [%0], [%1], 16;"
                 :: "r"(dst_smem), "l"(src));
}

__global__ void __launch_bounds__(TPB)
mask_head_kernel(const float* __restrict__ feat,
                 const float* __restrict__ params,
                 float* __restrict__ out) {
    extern __shared__ float4 fbuf[];   // [NSTAGE][CIN][TILE4]

    // Weights duplicated into both float2 halves (LDS.64 -> fma.rn.f32x2).
    __shared__ float2 w0s[CMID * CIN];
    __shared__ float2 w1s[CMID * CMID];
    __shared__ float2 w2s[CMID];
    __shared__ float2 b0s[CMID];
    __shared__ float2 b1s[CMID];
    __shared__ float2 b2s;

    const int inst = blockIdx.y;
    const int tid  = threadIdx.x;

    const float* p = params + inst * 169;
    for (int i = tid; i < 169; i += TPB) {
        float v = p[i];
        float2 vv = make_float2(v, v);
        if      (i < 80)  w0s[i]       = vv;
        else if (i < 144) w1s[i - 80]  = vv;
        else if (i < 152) w2s[i - 144] = vv;
        else if (i < 160) b0s[i - 152] = vv;
        else if (i < 168) b1s[i - 160] = vv;
        else              b2s          = vv;
    }
    __syncthreads();

    // This CTA's strip: tiles [t0, t0 + TILES_PER_CTA)
    const int t0 = blockIdx.x * TILES_PER_CTA;
    const float4* fin4 = reinterpret_cast<const float4*>(feat) + inst * CIN * HW4;
    float4* out4 = reinterpret_cast<float4*>(out) + inst * HW4;

    const uint32_t sbase = (uint32_t)__cvta_generic_to_shared(fbuf);

    // Issue all 20 cp.asyncs for one tile into one stage. Thread tid owns
    // float4 slots tid and tid+128 of each channel row.
    auto issue_tile = [&](int tile, int stage) {
        const float4* g = fin4 + (t0 + tile) * TILE4 + tid;
        uint32_t s = sbase + (stage * SMEM_TILE_F4 + tid) * 16;
#pragma unroll
        for (int k = 0; k < CIN; k++) {
            cp16(s,             g);
            cp16(s + 128 * 16,  g + 128);
            g += HW4;
            s += TILE4 * 16;
        }
        asm volatile("cp.async.commit_group;");
    };

    issue_tile(0, 0);
    issue_tile(1, 1);

#pragma unroll
    for (int t = 0; t < TILES_PER_CTA; t++) {
        const int stage = t & 1;
        if (t == TILES_PER_CTA - 1)
            asm volatile("cp.async.wait_group 0;");
        else
            asm volatile("cp.async.wait_group 1;");
        // Each thread consumes only slots it copied itself -> no barrier
        // needed for visibility (cp.async wait gives per-thread ordering).

        const float4* sb = fbuf + stage * SMEM_TILE_F4 + tid;

        // ---- Layer 0 (10 -> 8, ReLU) ----
        float2 h0[CMID][4];
#pragma unroll
        for (int o = 0; o < CMID; o++) {
            float2 b = b0s[o];
#pragma unroll
            for (int j = 0; j < 4; j++) h0[o][j] = b;
        }

#pragma unroll
        for (int k = 0; k < CIN; k++) {
            float4 v0 = sb[k * TILE4];
            float4 v1 = sb[k * TILE4 + 128];
            float2 x[4] = { make_float2(v0.x, v0.y), make_float2(v0.z, v0.w),
                            make_float2(v1.x, v1.y), make_float2(v1.z, v1.w) };
#pragma unroll
            for (int o = 0; o < CMID; o++) {
                float2 w = w0s[o * CIN + k];
#pragma unroll
                for (int j = 0; j < 4; j++) h0[o][j] = ffma2(w, x[j], h0[o][j]);
            }
        }
#pragma unroll
        for (int o = 0; o < CMID; o++)
#pragma unroll
            for (int j = 0; j < 4; j++) h0[o][j] = relu2(h0[o][j]);

        // ---- Layers 1+2 fused ----
        float2 acc[4];
        {
            float2 b = b2s;
#pragma unroll
            for (int j = 0; j < 4; j++) acc[j] = b;
        }
#pragma unroll
        for (int o = 0; o < CMID; o++) {
            float2 tt[4];
            float2 b = b1s[o];
#pragma unroll
            for (int j = 0; j < 4; j++) tt[j] = b;
#pragma unroll
            for (int k = 0; k < CMID; k++) {
                float2 w = w1s[o * CMID + k];
#pragma unroll
                for (int j = 0; j < 4; j++) tt[j] = ffma2(w, h0[k][j], tt[j]);
            }
            float2 w2 = w2s[o];
#pragma unroll
            for (int j = 0; j < 4; j++) acc[j] = ffma2(w2, relu2(tt[j]), acc[j]);
        }

        float4* ob = out4 + (t0 + t) * TILE4 + tid;
        ob[0]   = make_float4(acc[0].x, acc[0].y, acc[1].x, acc[1].y);
        ob[128] = make_float4(acc[2].x, acc[2].y, acc[3].x, acc[3].y);

        // Fence this thread's LDS reads of `stage` before refilling it.
        __syncthreads();
        if (t + NSTAGE < TILES_PER_CTA)
            issue_tile(t + NSTAGE, stage);
    }
}

extern "C" void kernel_launch(void* const* d_in, const int* in_sizes, int n_in,
                              void* d_out, int out_size) {
    const float* feat   = (const float*)d_in[0];
    const float* params = (const float*)d_in[1];
    float* out          = (float*)d_out;

    static bool configured = false;
    if (!configured) {
        cudaFuncSetAttribute(mask_head_kernel,
                             cudaFuncAttributeMaxDynamicSharedMemorySize,
                             DYN_SMEM_BYTES);
        configured = true;
    }

    dim3 grid(CTAS_X, NINST);   // (5, 128) = 640 CTAs
    mask_head_kernel<<<grid, TPB, DYN_SMEM_BYTES>>>(feat, params, out);
}

// round 7
// speedup vs baseline: 1.2373x; 1.2373x over previous
#include <cuda_runtime.h>
#include <cuda_bf16.h>
#include <cstdint>

// DynamicMaskHead: 128 instances, MLP 10 -> 8 -> 8 -> 1 over 160x160 px (fp32).
// Persistent pipelined version: 296 CTAs (exactly 2/SM, single wave), each
// owning a contiguous run of 10-11 tiles (1024 px each). Features stream
// through a 2-stage cp.async smem ring with NO block barriers in the loop
// (each thread reads only slots it copied; wait_group gives ordering).
// A run spans <=2 instances, so both weight sets are preloaded once into
// double-buffered smem (single __syncthreads for the whole kernel).

#define NINST 128
#define CIN   10
#define CMID  8
#define HW    25600
#define HW4   (HW / 4)
#define TPB   128
#define TILE4 256                       // float4 per tile (1024 px)
#define NSTAGE 2
#define NTILES_TOTAL 3200               // 25 tiles/inst * 128 inst
#define NCTA 296                        // 2 per SM, one wave

#define SMEM_TILE_F4 (CIN * TILE4)      // 2560 float4 per stage
#define DYN_SMEM_BYTES (NSTAGE * SMEM_TILE_F4 * 16)   // 81920

__device__ __forceinline__ float2 ffma2(float2 a, float2 b, float2 c) {
    float2 d;
    asm("fma.rn.f32x2 %0, %1, %2, %3;"
        : "=l"(reinterpret_cast<unsigned long long&>(d))
        : "l"(reinterpret_cast<unsigned long long&>(a)),
          "l"(reinterpret_cast<unsigned long long&>(b)),
          "l"(reinterpret_cast<unsigned long long&>(c)));
    return d;
}

__device__ __forceinline__ float2 relu2(float2 a) {
    return make_float2(fmaxf(a.x, 0.0f), fmaxf(a.y, 0.0f));
}

__device__ __forceinline__ void cp16(uint32_t dst_smem, const float4* src) {
    asm volatile("cp.async.cg.shared.global [%0], [%1], 16;"
                 :: "r"(dst_smem), "l"(src));
}

__global__ void __launch_bounds__(TPB)
mask_head_kernel(const float* __restrict__ feat,
                 const float* __restrict__ params,
                 float* __restrict__ out) {
    extern __shared__ float4 fbuf[];    // [NSTAGE][CIN][TILE4]

    // Double-buffered weights (one buffer per instance this CTA touches),
    // duplicated into both float2 halves: LDS.64 feeds fma.rn.f32x2 directly.
    __shared__ float2 w0s[2][CMID * CIN];
    __shared__ float2 w1s[2][CMID * CMID];
    __shared__ float2 w2s[2][CMID];
    __shared__ float2 b0s[2][CMID];
    __shared__ float2 b1s[2][CMID];
    __shared__ float2 b2s[2];

    const int tid = threadIdx.x;
    const int b   = blockIdx.x;

    // Contiguous work assignment: first 240 CTAs get 11 tiles, rest 10.
    int first, count;
    if (b < 240) { first = b * 11;              count = 11; }
    else         { first = 2640 + (b - 240) * 10; count = 10; }

    const int inst0 = first / 25;
    const int inst1 = (first + count - 1) / 25;   // inst0 or inst0+1

    const float4* fin4 = reinterpret_cast<const float4*>(feat);
    float4* out4 = reinterpret_cast<float4*>(out);
    const uint32_t sbase = (uint32_t)__cvta_generic_to_shared(fbuf);

    // Issue the 20 cp.asyncs of one tile-item into a stage; thread tid owns
    // float4 slots tid and tid+128 of each channel row.
    auto issue_item = [&](int item, int stage) {
        const int inst = item / 25;
        const int tile = item % 25;
        const float4* g = fin4 + inst * CIN * HW4 + tile * TILE4 + tid;
        uint32_t s = sbase + (stage * SMEM_TILE_F4 + tid) * 16;
#pragma unroll
        for (int k = 0; k < CIN; k++) {
            cp16(s,            g);
            cp16(s + 128 * 16, g + 128);
            g += HW4;
            s += TILE4 * 16;
        }
        asm volatile("cp.async.commit_group;");
    };

    // Prime the feature pipeline first so DRAM starts streaming immediately.
    int issued = 0;
    issue_item(first, 0); issued = 1;
    if (count > 1) { issue_item(first + 1, 1); issued = 2; }

    // Preload both instances' weight sets (overlapped with the cp.asyncs).
    for (int i = tid; i < 169; i += TPB) {
        float va = params[inst0 * 169 + i];
        float vb = params[inst1 * 169 + i];
        float2 a2 = make_float2(va, va);
        float2 b2v = make_float2(vb, vb);
        if      (i < 80)  { w0s[0][i]       = a2; w0s[1][i]       = b2v; }
        else if (i < 144) { w1s[0][i - 80]  = a2; w1s[1][i - 80]  = b2v; }
        else if (i < 152) { w2s[0][i - 144] = a2; w2s[1][i - 144] = b2v; }
        else if (i < 160) { b0s[0][i - 152] = a2; b0s[1][i - 152] = b2v; }
        else if (i < 168) { b1s[0][i - 160] = a2; b1s[1][i - 160] = b2v; }
        else              { b2s[0]          = a2; b2s[1]          = b2v; }
    }
    __syncthreads();   // the only block barrier in the kernel

    for (int i = 0; i < count; i++) {
        const int item = first + i;
        const int inst = item / 25;
        const int tile = item % 25;
        const int wsel = (inst != inst0) ? 1 : 0;
        const int stage = i & 1;

        // Wait until this item's group has landed (per-thread ordering).
        if (issued > i + 1) asm volatile("cp.async.wait_group 1;");
        else                asm volatile("cp.async.wait_group 0;");

        const float4* sb = fbuf + stage * SMEM_TILE_F4 + tid;
        const float2* w0p = w0s[wsel];
        const float2* w1p = w1s[wsel];
        const float2* w2p = w2s[wsel];
        const float2* b0p = b0s[wsel];
        const float2* b1p = b1s[wsel];

        // ---- Layer 0 (10 -> 8, ReLU) ----
        float2 h0[CMID][4];
#pragma unroll
        for (int o = 0; o < CMID; o++) {
            float2 bb = b0p[o];
#pragma unroll
            for (int j = 0; j < 4; j++) h0[o][j] = bb;
        }
#pragma unroll
        for (int k = 0; k < CIN; k++) {
            float4 v0 = sb[k * TILE4];
            float4 v1 = sb[k * TILE4 + 128];
            float2 x[4] = { make_float2(v0.x, v0.y), make_float2(v0.z, v0.w),
                            make_float2(v1.x, v1.y), make_float2(v1.z, v1.w) };
#pragma unroll
            for (int o = 0; o < CMID; o++) {
                float2 w = w0p[o * CIN + k];
#pragma unroll
                for (int j = 0; j < 4; j++) h0[o][j] = ffma2(w, x[j], h0[o][j]);
            }
        }
#pragma unroll
        for (int o = 0; o < CMID; o++)
#pragma unroll
            for (int j = 0; j < 4; j++) h0[o][j] = relu2(h0[o][j]);

        // ---- Layers 1+2 fused ----
        float2 acc[4];
        {
            float2 bb = b2s[wsel];
#pragma unroll
            for (int j = 0; j < 4; j++) acc[j] = bb;
        }
#pragma unroll
        for (int o = 0; o < CMID; o++) {
            float2 t[4];
            float2 bb = b1p[o];
#pragma unroll
            for (int j = 0; j < 4; j++) t[j] = bb;
#pragma unroll
            for (int k = 0; k < CMID; k++) {
                float2 w = w1p[o * CMID + k];
#pragma unroll
                for (int j = 0; j < 4; j++) t[j] = ffma2(w, h0[k][j], t[j]);
            }
            float2 w2 = w2p[o];
#pragma unroll
            for (int j = 0; j < 4; j++) acc[j] = ffma2(w2, relu2(t[j]), acc[j]);
        }

        float4* ob = out4 + inst * HW4 + tile * TILE4 + tid;
        ob[0]   = make_float4(acc[0].x, acc[0].y, acc[1].x, acc[1].y);
        ob[128] = make_float4(acc[2].x, acc[2].y, acc[3].x, acc[3].y);

        // Refill the stage just freed. Safe without a barrier: only this
        // thread touches these slots, and its LDS reads were consumed by the
        // FFMAs above (true data dependency) before this issue point.
        if (issued < count) { issue_item(first + issued, issued & 1); issued++; }
    }
}

extern "C" void kernel_launch(void* const* d_in, const int* in_sizes, int n_in,
                              void* d_out, int out_size) {
    const float* feat   = (const float*)d_in[0];
    const float* params = (const float*)d_in[1];
    float* out          = (float*)d_out;

    cudaFuncSetAttribute(mask_head_kernel,
                         cudaFuncAttributeMaxDynamicSharedMemorySize,
                         DYN_SMEM_BYTES);

    mask_head_kernel<<<NCTA, TPB, DYN_SMEM_BYTES>>>(feat, params, out);
}

// round 8
// speedup vs baseline: 1.3034x; 1.0534x over previous
#include <cuda_runtime.h>
#include <cuda_bf16.h>
#include <cstdint>

// DynamicMaskHead: 128 instances, MLP 10 -> 8 -> 8 -> 1 over 160x160 px (fp32).
// Persistent barrier-free cp.async pipeline (R7 structure) re-tiled for
// occupancy: tile = 512 px, 4 px/thread, 4 CTAs/SM (592 CTAs, one wave),
// 16 warps/SM = 4 warps/SMSP to fill dependency-stall holes.

#define NINST 128
#define CIN   10
#define CMID  8
#define HW    25600
#define HW4   (HW / 4)
#define TPB   128
#define TILE4 128                       // float4 per tile (512 px)
#define TILES_PER_INST 50
#define NTILES_TOTAL 6400
#define NSTAGE 2
#define NCTA 592                        // 4 per SM, one wave

#define SMEM_TILE_F4 (CIN * TILE4)      // 1280 float4 per stage (20 KB)
#define DYN_SMEM_BYTES (NSTAGE * SMEM_TILE_F4 * 16)   // 40960

__device__ __forceinline__ float2 ffma2(float2 a, float2 b, float2 c) {
    float2 d;
    asm("fma.rn.f32x2 %0, %1, %2, %3;"
        : "=l"(reinterpret_cast<unsigned long long&>(d))
        : "l"(reinterpret_cast<unsigned long long&>(a)),
          "l"(reinterpret_cast<unsigned long long&>(b)),
          "l"(reinterpret_cast<unsigned long long&>(c)));
    return d;
}

__device__ __forceinline__ float2 relu2(float2 a) {
    return make_float2(fmaxf(a.x, 0.0f), fmaxf(a.y, 0.0f));
}

__device__ __forceinline__ void cp16(uint32_t dst_smem, const float4* src) {
    asm volatile("cp.async.cg.shared.global [%0], [%1], 16;"
                 :: "r"(dst_smem), "l"(src));
}

__global__ void __launch_bounds__(TPB, 4)
mask_head_kernel(const float* __restrict__ feat,
                 const float* __restrict__ params,
                 float* __restrict__ out) {
    extern __shared__ float4 fbuf[];    // [NSTAGE][CIN][TILE4]

    // Double-buffered weight sets (a CTA's tile run spans <= 2 instances),
    // duplicated into both float2 halves: LDS.64 (broadcast) feeds fma.rn.f32x2.
    __shared__ float2 w0s[2][CMID * CIN];
    __shared__ float2 w1s[2][CMID * CMID];
    __shared__ float2 w2s[2][CMID];
    __shared__ float2 b0s[2][CMID];
    __shared__ float2 b1s[2][CMID];
    __shared__ float2 b2s[2];

    const int tid = threadIdx.x;
    const int b   = blockIdx.x;

    // 6400 tiles over 592 CTAs: first 480 CTAs get 11, remaining 112 get 10.
    int first, count;
    if (b < 480) { first = b * 11;               count = 11; }
    else         { first = 5280 + (b - 480) * 10; count = 10; }

    const int inst0 = first / TILES_PER_INST;
    const int inst1 = (first + count - 1) / TILES_PER_INST;  // inst0 or inst0+1

    const float4* fin4 = reinterpret_cast<const float4*>(feat);
    float4* out4 = reinterpret_cast<float4*>(out);
    const uint32_t sbase = (uint32_t)__cvta_generic_to_shared(fbuf);

    // 10 cp.asyncs per item; thread tid owns float4 slot tid of each channel.
    auto issue_item = [&](int item, int stage) {
        const int inst = item / TILES_PER_INST;
        const int tile = item % TILES_PER_INST;
        const float4* g = fin4 + inst * CIN * HW4 + tile * TILE4 + tid;
        uint32_t s = sbase + (stage * SMEM_TILE_F4 + tid) * 16;
#pragma unroll
        for (int k = 0; k < CIN; k++) {
            cp16(s, g);
            g += HW4;
            s += TILE4 * 16;
        }
        asm volatile("cp.async.commit_group;");
    };

    // Prime the pipeline so DRAM streams immediately.
    int issued = 0;
    issue_item(first, 0); issued = 1;
    if (count > 1) { issue_item(first + 1, 1); issued = 2; }

    // Preload both weight sets (overlapped with the primed cp.asyncs).
    for (int i = tid; i < 169; i += TPB) {
        float va = params[inst0 * 169 + i];
        float vb = params[inst1 * 169 + i];
        float2 a2  = make_float2(va, va);
        float2 b2v = make_float2(vb, vb);
        if      (i < 80)  { w0s[0][i]       = a2; w0s[1][i]       = b2v; }
        else if (i < 144) { w1s[0][i - 80]  = a2; w1s[1][i - 80]  = b2v; }
        else if (i < 152) { w2s[0][i - 144] = a2; w2s[1][i - 144] = b2v; }
        else if (i < 160) { b0s[0][i - 152] = a2; b0s[1][i - 152] = b2v; }
        else if (i < 168) { b1s[0][i - 160] = a2; b1s[1][i - 160] = b2v; }
        else              { b2s[0]          = a2; b2s[1]          = b2v; }
    }
    __syncthreads();   // only block barrier in the kernel

    for (int i = 0; i < count; i++) {
        const int item = first + i;
        const int inst = item / TILES_PER_INST;
        const int tile = item % TILES_PER_INST;
        const int wsel = (inst != inst0) ? 1 : 0;
        const int stage = i & 1;

        // Wait for this item's group (groups complete in order; per-thread).
        if (issued > i + 1) asm volatile("cp.async.wait_group 1;");
        else                asm volatile("cp.async.wait_group 0;");

        const float4* sb = fbuf + stage * SMEM_TILE_F4 + tid;
        const float2* w0p = w0s[wsel];
        const float2* w1p = w1s[wsel];
        const float2* w2p = w2s[wsel];
        const float2* b0p = b0s[wsel];
        const float2* b1p = b1s[wsel];

        // ---- Layer 0 (10 -> 8, ReLU), 4 px = 2 f32x2 lanes ----
        float2 h0[CMID][2];
#pragma unroll
        for (int o = 0; o < CMID; o++) {
            float2 bb = b0p[o];
            h0[o][0] = bb; h0[o][1] = bb;
        }
#pragma unroll
        for (int k = 0; k < CIN; k++) {
            float4 v = sb[k * TILE4];
            float2 x0 = make_float2(v.x, v.y);
            float2 x1 = make_float2(v.z, v.w);
#pragma unroll
            for (int o = 0; o < CMID; o++) {
                float2 w = w0p[o * CIN + k];
                h0[o][0] = ffma2(w, x0, h0[o][0]);
                h0[o][1] = ffma2(w, x1, h0[o][1]);
            }
        }
#pragma unroll
        for (int o = 0; o < CMID; o++) {
            h0[o][0] = relu2(h0[o][0]);
            h0[o][1] = relu2(h0[o][1]);
        }

        // ---- Layers 1+2 fused ----
        float2 acc0, acc1;
        {
            float2 bb = b2s[wsel];
            acc0 = bb; acc1 = bb;
        }
#pragma unroll
        for (int o = 0; o < CMID; o++) {
            float2 bb = b1p[o];
            float2 t0 = bb, t1 = bb;
#pragma unroll
            for (int k = 0; k < CMID; k++) {
                float2 w = w1p[o * CMID + k];
                t0 = ffma2(w, h0[k][0], t0);
                t1 = ffma2(w, h0[k][1], t1);
            }
            float2 w2 = w2p[o];
            acc0 = ffma2(w2, relu2(t0), acc0);
            acc1 = ffma2(w2, relu2(t1), acc1);
        }

        out4[inst * HW4 + tile * TILE4 + tid] =
            make_float4(acc0.x, acc0.y, acc1.x, acc1.y);

        // Refill the freed stage (no barrier: this thread's slots only, and
        // its LDS reads were consumed by the FFMAs above).
        if (issued < count) { issue_item(first + issued, issued & 1); issued++; }
    }
}

extern "C" void kernel_launch(void* const* d_in, const int* in_sizes, int n_in,
                              void* d_out, int out_size) {
    const float* feat   = (const float*)d_in[0];
    const float* params = (const float*)d_in[1];
    float* out          = (float*)d_out;

    cudaFuncSetAttribute(mask_head_kernel,
                         cudaFuncAttributeMaxDynamicSharedMemorySize,
                         DYN_SMEM_BYTES);

    mask_head_kernel<<<NCTA, TPB, DYN_SMEM_BYTES>>>(feat, params, out);
}